// round 3
// baseline (speedup 1.0000x reference)
#include <cuda_runtime.h>
#include <cstdint>

// Wilson-Cowan rate recurrence, B=8, T=4096, N=1024.
//   Phi(x) = M*x/(x^2+sigma^2) * relu(x+th)
//   nu_{t+1} = (1-dt/tau)*nu_t + (dt/tau)*Phi(E_t - r*nu_t)
// One thread per (b,n) channel, serial over T.
// E is staged through shared memory with a cp.async 3-stage pipeline so the
// load->use distance is not limited by the 6 SASS scoreboard slots.

#define CW_B 8
#define CW_T 4096
#define CW_N 1024
#define CW_DT 0.1f

#define K_TILE 32              // time steps per tile
#define STAGES 3               // pipeline depth
#define CTA_CH 64              // channels per CTA == blockDim.x
#define F4_PER_TILE (K_TILE * CTA_CH / 4)   // 512 float4 per tile
#define PASSES (F4_PER_TILE / CTA_CH)       // 8 cp.async per thread per tile

__device__ __forceinline__ void cp_async16(void* smem_dst, const void* gmem_src) {
    unsigned saddr = (unsigned)__cvta_generic_to_shared(smem_dst);
    asm volatile("cp.async.cg.shared.global [%0], [%1], 16;\n"
                 :: "r"(saddr), "l"(gmem_src));
}
__device__ __forceinline__ void cp_commit() {
    asm volatile("cp.async.commit_group;\n" ::: "memory");
}
template <int Npend>
__device__ __forceinline__ void cp_wait() {
    asm volatile("cp.async.wait_group %0;\n" :: "n"(Npend) : "memory");
}

__global__ __launch_bounds__(CTA_CH, 1)
void cw_recurrence_kernel(const float* __restrict__ E,
                          const float* __restrict__ r,
                          const float* __restrict__ tau_nu,
                          const float* __restrict__ M,
                          const float* __restrict__ sigma,
                          const float* __restrict__ th,
                          float* __restrict__ out)
{
    __shared__ float4 sbuf[STAGES][F4_PER_TILE];

    const int tid = threadIdx.x;
    const int ch0 = blockIdx.x * CTA_CH;      // first channel of this CTA
    const int ch  = ch0 + tid;                // 0..8191
    const int b   = ch >> 10;                 // CTA_CH divides N, so b uniform per CTA
    const int n   = ch & (CW_N - 1);
    const int n0  = ch0 & (CW_N - 1);

    // Per-channel constants (off the recurrence chain)
    const float rr   = r[n];
    const float coef = CW_DT / tau_nu[n];
    const float a    = 1.0f - coef;
    const float cM   = coef * M[n];
    const float s    = sigma[n];
    const float sig2 = s * s;
    const float thv  = th[n];

    const float* eBase = E   + (size_t)b * CW_T * CW_N + n0;   // tile origin
    float*       oPtr  = out + (size_t)b * CW_T * CW_N + n;

    // ---- async tile loader: E[b, tile*K : tile*K+K, n0:n0+CTA_CH] -> sbuf[stage]
    auto load_tile = [&](int tile, int stage) {
        const float* src = eBase + (size_t)tile * K_TILE * CW_N;
        #pragma unroll
        for (int p = 0; p < PASSES; ++p) {
            int idx = p * CTA_CH + tid;      // 0..511
            int j   = idx >> 4;              // time row (16 float4 per row)
            int c4  = idx & 15;              // float4 column
            cp_async16(&sbuf[stage][j * 16 + c4],
                       src + (size_t)j * CW_N + (c4 << 2));
        }
    };

    // Prologue: fill the pipeline
    #pragma unroll
    for (int s0 = 0; s0 < STAGES; ++s0) {
        load_tile(s0, s0);
        cp_commit();
    }

    float nu = 0.0f;
    const int NT = CW_T / K_TILE;            // 128 tiles

    for (int tile = 0; tile < NT; ++tile) {
        cp_wait<STAGES - 1>();               // tile's group complete
        __syncthreads();

        const int stage = tile % STAGES;
        const float* sf = (const float*)&sbuf[stage][0];
        float* op = oPtr + (size_t)tile * K_TILE * CW_N;

        #pragma unroll
        for (int j = 0; j < K_TILE; ++j) {
            const float e = sf[j * CTA_CH + tid];

            // critical path: u -> d -> rcp -> fma  (~28 cyc)
            const float u  = fmaf(-rr, nu, e);       // e - r*nu
            const float d  = fmaf(u, u, sig2);       // u^2 + sigma^2
            float ri;
            asm("rcp.approx.f32 %0, %1;" : "=f"(ri) : "f"(d));

            // off-chain, runs in parallel with rcp
            const float an = a * nu;
            const float rl = fmaxf(u + thv, 0.0f);
            const float p  = cM * u * rl;

            nu = fmaf(p, ri, an);
            op[(size_t)j * CW_N] = nu;
        }

        __syncthreads();                     // all readers done with this stage
        const int nxt = tile + STAGES;
        if (nxt < NT) load_tile(nxt, stage);
        cp_commit();                         // always commit to keep group count in sync
    }
}

extern "C" void kernel_launch(void* const* d_in, const int* in_sizes, int n_in,
                              void* d_out, int out_size)
{
    const float* E      = (const float*)d_in[0];
    const float* r      = (const float*)d_in[1];
    const float* tau_nu = (const float*)d_in[2];
    const float* M      = (const float*)d_in[3];
    const float* sigma  = (const float*)d_in[4];
    const float* th     = (const float*)d_in[5];
    float* out = (float*)d_out;

    // 8192 channels / 64 per CTA = 128 CTAs
    cw_recurrence_kernel<<<(CW_B * CW_N) / CTA_CH, CTA_CH>>>(E, r, tau_nu, M, sigma, th, out);
}

// round 4
// speedup vs baseline: 2.4946x; 2.4946x over previous
#include <cuda_runtime.h>
#include <cstdint>

// Wilson-Cowan rate recurrence, B=8, T=4096, N=1024.
//   Phi(x) = M*x/(x^2+sigma^2) * relu(x+th)
//   nu_{t+1} = (1-dt/tau)*nu_t + (dt/tau)*Phi(E_t - r*nu_t)
//
// Parallel-in-time: T split into CHUNKS chunks of L steps. Chunks c>0 start
// from nu=0 at t = c*L - WARM and integrate WARM discarded warm-up steps;
// the map is contracting (|d nu'/d nu| ~ 0.93), so 0.93^320 ~ 1e-10 of the
// initial state error survives at the chunk seam.
//
// E staged through a per-warp cp.async pipeline (no CTA barriers at all).

#define CW_B 8
#define CW_T 4096
#define CW_N 1024
#define CW_DT 0.1f

#define CHUNKS 4
#define CW_L   (CW_T / CHUNKS)   // 1024 output steps per chunk
#define WARM   320               // warm-up steps (multiple of K_TILE)

#define K_TILE 32                // time steps per tile
#define STAGES 3                 // pipeline depth
#define CTA_CH 64                // channels per CTA (2 warps)
#define WARPS  (CTA_CH / 32)
#define F4_PER_WARP_TILE (K_TILE * 32 / 4)   // 256 float4 per warp-tile
#define PASSES (F4_PER_WARP_TILE / 32)       // 8 cp.async per lane per tile

__device__ __forceinline__ void cp_async16(void* smem_dst, const void* gmem_src) {
    unsigned saddr = (unsigned)__cvta_generic_to_shared(smem_dst);
    asm volatile("cp.async.cg.shared.global [%0], [%1], 16;\n"
                 :: "r"(saddr), "l"(gmem_src));
}
__device__ __forceinline__ void cp_commit() {
    asm volatile("cp.async.commit_group;\n" ::: "memory");
}
template <int Npend>
__device__ __forceinline__ void cp_wait() {
    asm volatile("cp.async.wait_group %0;\n" :: "n"(Npend) : "memory");
}

__global__ __launch_bounds__(CTA_CH, 1)
void cw_recurrence_kernel(const float* __restrict__ E,
                          const float* __restrict__ r,
                          const float* __restrict__ tau_nu,
                          const float* __restrict__ M,
                          const float* __restrict__ sigma,
                          const float* __restrict__ th,
                          float* __restrict__ out)
{
    // [stage][warp][256 float4]  (each warp owns its own 4KB tile slice)
    __shared__ float4 sbuf[STAGES][WARPS][F4_PER_WARP_TILE];

    const int tid   = threadIdx.x;
    const int w     = tid >> 5;
    const int lane  = tid & 31;

    const int nCtaPerCh = (CW_B * CW_N) / CTA_CH;        // 128
    const int chunk = blockIdx.x / nCtaPerCh;            // 0..CHUNKS-1
    const int cta   = blockIdx.x % nCtaPerCh;

    const int ch0 = cta * CTA_CH;                        // first channel of CTA
    const int ch  = ch0 + tid;
    const int b   = ch >> 10;                            // batch (uniform per CTA)
    const int n   = ch & (CW_N - 1);
    const int nw0 = (ch0 & (CW_N - 1)) + 32 * w;         // first channel of warp

    // Per-channel constants (off the recurrence chain)
    const float rr   = r[n];
    const float coef = CW_DT / tau_nu[n];
    const float a    = 1.0f - coef;
    const float cM   = coef * M[n];
    const float s    = sigma[n];
    const float sig2 = s * s;
    const float thv  = th[n];

    const int warm    = (chunk == 0) ? 0 : WARM;
    const int t0      = chunk * CW_L - warm;             // first integrated step
    const int nsteps  = CW_L + warm;
    const int NT      = nsteps / K_TILE;                 // tiles this chunk
    const int warm_nt = warm / K_TILE;                   // tiles with no store

    const float* eWarp = E   + ((size_t)b * CW_T + t0) * CW_N + nw0;
    float*       oPtr  = out + ((size_t)b * CW_T + t0) * CW_N + n;

    // per-warp async tile load: rows [tile*K, tile*K+K), channels [nw0, nw0+32)
    auto load_tile = [&](int tile, int stage) {
        const float* src = eWarp + (size_t)tile * K_TILE * CW_N;
        #pragma unroll
        for (int p = 0; p < PASSES; ++p) {
            int idx = p * 32 + lane;         // 0..255
            int j   = idx >> 3;              // time row (8 float4 per row)
            int c4  = idx & 7;
            cp_async16(&sbuf[stage][w][j * 8 + c4],
                       src + (size_t)j * CW_N + (c4 << 2));
        }
    };

    #pragma unroll
    for (int s0 = 0; s0 < STAGES; ++s0) {
        load_tile(s0, s0);
        cp_commit();
    }

    float nu = 0.0f;

    for (int tile = 0; tile < NT; ++tile) {
        cp_wait<STAGES - 1>();               // this tile's group complete (per-thread)

        const int stage = tile % STAGES;
        const float* sf = (const float*)&sbuf[stage][w][0];
        float* op = oPtr + (size_t)tile * K_TILE * CW_N;
        const bool do_store = (tile >= warm_nt);

        #pragma unroll
        for (int j = 0; j < K_TILE; ++j) {
            const float e = sf[j * 32 + lane];

            // critical path: u -> d -> rcp -> fma  (~28 cyc)
            const float u  = fmaf(-rr, nu, e);       // e - r*nu
            const float d  = fmaf(u, u, sig2);       // u^2 + sigma^2
            float ri;
            asm("rcp.approx.f32 %0, %1;" : "=f"(ri) : "f"(d));

            // off-chain, overlaps the rcp
            const float an = a * nu;
            const float rl = fmaxf(u + thv, 0.0f);
            const float p  = cM * u * rl;

            nu = fmaf(p, ri, an);
            if (do_store) op[(size_t)j * CW_N] = nu;
        }

        const int nxt = tile + STAGES;
        if (nxt < NT) load_tile(nxt, stage); // warp-private: no __syncthreads needed
        cp_commit();                         // keep group count consistent
    }
}

extern "C" void kernel_launch(void* const* d_in, const int* in_sizes, int n_in,
                              void* d_out, int out_size)
{
    const float* E      = (const float*)d_in[0];
    const float* r      = (const float*)d_in[1];
    const float* tau_nu = (const float*)d_in[2];
    const float* M      = (const float*)d_in[3];
    const float* sigma  = (const float*)d_in[4];
    const float* th     = (const float*)d_in[5];
    float* out = (float*)d_out;

    // 128 CTAs per chunk x 4 chunks = 512 CTAs, 64 threads each
    cw_recurrence_kernel<<<((CW_B * CW_N) / CTA_CH) * CHUNKS, CTA_CH>>>(
        E, r, tau_nu, M, sigma, th, out);
}